// round 9
// baseline (speedup 1.0000x reference)
#include <cuda_runtime.h>
#include <cuda_bf16.h>

// Fractal2DDiff — SIMT f32x2 v4: dup'd tables => zero-mov hot loop.
//  * D,R stored in smem as duplicated f32x2 pairs -> FMA2 operands come
//    straight out of LDS.128 (no PACK_DUP/UNPACK2 in the inner loop).
//  * rank-1 analytic first step, folded final step (D@CP, R@CP), one
//    normalization at the end (L,R row-stochastic; CP rows sum to 1).
//  * 8 warps / 256 threads, 222KB smem, one CTA per SM.

#define N_NODES   64
#define N_CLASSES 16
#define WARPS     8
#define TPB       (WARPS * 32)
#define PSTRIDE   36   // floats per p/left row (32 + pad); must be mult of 4

typedef unsigned long long u64;

__device__ ulonglong2 g_Dd[2048];             // dup pairs (d,d): [64][64] -> 32KB
__device__ ulonglong2 g_Rd[2048];             // dup pairs (r,r)
__device__ float g_DC[N_NODES * N_CLASSES];   // (L-R) @ CP
__device__ float g_RC[N_NODES * N_CLASSES];   // R @ CP
__device__ float g_par[256];                  // exp(-sp) | dirs | D row0 | R row0

// ---------------------------------------------------------------------------
__global__ void fractal_setup_kernel(const float* __restrict__ sp,
                                     const float* __restrict__ dir_logits,
                                     const float* __restrict__ class_logits,
                                     const float* __restrict__ child_logits) {
    __shared__ float sCP[N_NODES * N_CLASSES];
    int t = threadIdx.x;   // 64 threads, t = node

    {   // CP row t
        const float* cr = class_logits + t * N_CLASSES;
        float m = -1e30f;
        for (int i = 0; i < N_CLASSES; i++) m = fmaxf(m, cr[i]);
        float s = 0.0f;
        for (int i = 0; i < N_CLASSES; i++) s += expf(cr[i] - m);
        float inv = 1.0f / s;
        for (int i = 0; i < N_CLASSES; i++) sCP[t * N_CLASSES + i] = expf(cr[i] - m) * inv;
    }
    __syncthreads();

    const float* lr = child_logits + (size_t)t * 2 * N_NODES;
    const float* rr = lr + N_NODES;
    float Lv[64], Rv[64], Dv[64];
    {
        float m = -1e30f;
        for (int i = 0; i < 64; i++) m = fmaxf(m, lr[i]);
        float s = 0.0f;
        for (int i = 0; i < 64; i++) s += expf(lr[i] - m);
        float inv = 1.0f / s;
        for (int i = 0; i < 64; i++) Lv[i] = expf(lr[i] - m) * inv;
    }
    {
        float m = -1e30f;
        for (int i = 0; i < 64; i++) m = fmaxf(m, rr[i]);
        float s = 0.0f;
        for (int i = 0; i < 64; i++) s += expf(rr[i] - m);
        float inv = 1.0f / s;
        for (int i = 0; i < 64; i++) Rv[i] = expf(rr[i] - m) * inv;
    }
    u64* Dd = reinterpret_cast<u64*>(g_Dd);
    u64* Rd = reinterpret_cast<u64*>(g_Rd);
    for (int i = 0; i < 64; i++) {
        Dv[i] = Lv[i] - Rv[i];
        u64 db = (u64)__float_as_uint(Dv[i]);
        u64 rb = (u64)__float_as_uint(Rv[i]);
        Dd[t * 64 + i] = (db << 32) | db;   // (d,d)
        Rd[t * 64 + i] = (rb << 32) | rb;   // (r,r)
    }
    for (int jc = 0; jc < N_CLASSES; jc++) {
        float ds = 0.0f, rs = 0.0f;
        for (int j = 0; j < 64; j++) {
            ds += Dv[j] * sCP[j * N_CLASSES + jc];
            rs += Rv[j] * sCP[j * N_CLASSES + jc];
        }
        g_DC[t * N_CLASSES + jc] = ds;
        g_RC[t * N_CLASSES + jc] = rs;
    }
    g_par[t]      = expf(-sp[t]);
    g_par[64 + t] = 1.0f / (1.0f + expf(-dir_logits[t]));
    // D row0 / R row0 (only thread 0 has row 0 values)
    if (t == 0)
        for (int j = 0; j < 64; j++) { g_par[128 + j] = Dv[j]; g_par[192 + j] = Rv[j]; }
}

// Packed f32x2 helpers (sm_103a)
#define FMA2(acc, a, b) \
    asm("fma.rn.f32x2 %0, %1, %2, %0;" : "+l"(acc) : "l"(a), "l"(b))
#define MUL2(d, a, b) \
    asm("mul.rn.f32x2 %0, %1, %2;" : "=l"(d) : "l"(a), "l"(b))
#define PACK_DUP(d, s) \
    asm("mov.b64 %0, {%1, %1};" : "=l"(d) : "f"(s))
#define UNPACK2(lo, hi, v) \
    asm("mov.b64 {%0, %1}, %2;" : "=f"(lo), "=f"(hi) : "l"(v))

__device__ __forceinline__ int decode_depth(const void* mdp) {
    int v = *reinterpret_cast<const int*>(mdp);
    if (v >= 1 && v <= 1000) return v;
    float f = __int_as_float(v);
    if (f >= 1.0f && f <= 1000.0f) return (int)f;
    return 10;
}

// smem floats: Dd 8192 | Rd 8192 | DCs 1024 | RCs 1024 | PAR 256 |
//              state WARPS * 2 * 64 * PSTRIDE
#define SMEM_FLOATS (8192 + 8192 + 1024 + 1024 + 256 + WARPS * 2 * 64 * PSTRIDE)
#define SMEM_BYTES  (SMEM_FLOATS * 4)

__global__ __launch_bounds__(TPB, 1)
void fractal_main_kernel(const float* __restrict__ x_pos,
                         const float* __restrict__ y_pos,
                         const void*  __restrict__ max_depth_ptr,
                         float* __restrict__ out,
                         int B) {
    extern __shared__ float sm[];
    u64*   Dd  = reinterpret_cast<u64*>(sm);          // [64][64] dup pairs
    u64*   Rd  = Dd + 4096;                           // [64][64] dup pairs
    float* DCs = sm + 16384;
    float* RCs = DCs + 1024;
    float* PAR = RCs + 1024;
    float* ST  = PAR + 256;

    const int tid  = threadIdx.x;
    const int wid  = tid >> 5;
    const int lane = tid & 31;
    const int cg   = lane & 7;    // col group
    const int pg   = lane >> 3;   // point group (4 groups x 8 pts)

    {   // cooperative table load (uint4 = 2 dup pairs)
        uint4* d4 = reinterpret_cast<uint4*>(Dd);
        uint4* r4 = reinterpret_cast<uint4*>(Rd);
        const uint4* gd = reinterpret_cast<const uint4*>(g_Dd);
        const uint4* gr = reinterpret_cast<const uint4*>(g_Rd);
        for (int i = tid; i < 2048; i += TPB) { d4[i] = gd[i]; r4[i] = gr[i]; }
        for (int i = tid; i < 1024; i += TPB) { DCs[i] = g_DC[i]; RCs[i] = g_RC[i]; }
        if (tid < 256) PAR[tid] = g_par[tid];
    }
    __syncthreads();

    float* Pw  = ST + wid * (2 * 64 * PSTRIDE);
    float* Lfw = Pw + 64 * PSTRIDE;

    const long long my_pt = (long long)blockIdx.x * TPB + wid * 32 + lane;
    const bool inr = (my_pt < B);

    int md = decode_depth(max_depth_ptr);
    if (md < 2) md = 2;
    const int full_iters = md - 2;

    const float x = inr ? x_pos[my_pt] : 0.5f;
    const float y = inr ? y_pos[my_pt] : 0.5f;
    const float ex = __expf(x), ey = __expf(y);

    // left[n] for own point (own smem column, no cross-thread hazard)
    #pragma unroll 8
    for (int n = 0; n < N_NODES; ++n) {
        float tn = PAR[n], d = PAR[64 + n];
        float hl = __fdividef(1.0f, 1.0f + ex * tn);   // sigmoid(sp-x)
        float vl = __fdividef(1.0f, 1.0f + ey * tn);   // sigmoid(sp-y)
        Lfw[n * PSTRIDE + lane] = hl + d * (vl - hl);
    }
    // rank-1 first step: p1 = R[0,:] + left0 * D[0,:]
    float l0;
    {
        float t0 = PAR[0], d0 = PAR[64];
        float hl = __fdividef(1.0f, 1.0f + ex * t0);
        float vl = __fdividef(1.0f, 1.0f + ey * t0);
        l0 = hl + d0 * (vl - hl);
    }
    #pragma unroll 8
    for (int n = 0; n < N_NODES; ++n)
        Pw[n * PSTRIDE + lane] = fmaf(l0, PAR[128 + n], PAR[192 + n]);
    __syncwarp();

    // ------- full iterations: acc[c][q], c=8 cols, q=4 point-pairs -------
    for (int it = 0; it < full_iters; ++it) {
        u64 acc[8][4];
        #pragma unroll
        for (int c = 0; c < 8; c++)
            #pragma unroll
            for (int q = 0; q < 4; q++) acc[c][q] = 0ull;

        #pragma unroll 2
        for (int n = 0; n < N_NODES; ++n) {
            const u64* drow = Dd + n * 64;
            const u64* rrow = Rd + n * 64;
            // dup-pair table loads: directly FMA2-ready, no movs
            ulonglong2 da  = *reinterpret_cast<const ulonglong2*>(drow + 4 * cg);
            ulonglong2 db  = *reinterpret_cast<const ulonglong2*>(drow + 4 * cg + 2);
            ulonglong2 dc  = *reinterpret_cast<const ulonglong2*>(drow + 32 + 4 * cg);
            ulonglong2 dd4 = *reinterpret_cast<const ulonglong2*>(drow + 34 + 4 * cg);
            ulonglong2 ra  = *reinterpret_cast<const ulonglong2*>(rrow + 4 * cg);
            ulonglong2 rb  = *reinterpret_cast<const ulonglong2*>(rrow + 4 * cg + 2);
            ulonglong2 rc  = *reinterpret_cast<const ulonglong2*>(rrow + 32 + 4 * cg);
            ulonglong2 rd4 = *reinterpret_cast<const ulonglong2*>(rrow + 34 + 4 * cg);

            const float* prow = Pw  + n * PSTRIDE + 8 * pg;
            const float* lrow = Lfw + n * PSTRIDE + 8 * pg;
            ulonglong2 pA = *reinterpret_cast<const ulonglong2*>(prow);
            ulonglong2 pB = *reinterpret_cast<const ulonglong2*>(prow + 4);
            ulonglong2 lA = *reinterpret_cast<const ulonglong2*>(lrow);
            ulonglong2 lB = *reinterpret_cast<const ulonglong2*>(lrow + 4);

            u64 p2[4] = { pA.x, pA.y, pB.x, pB.y };
            u64 l2[4] = { lA.x, lA.y, lB.x, lB.y };
            u64 a2[4];
            #pragma unroll
            for (int q = 0; q < 4; q++) MUL2(a2[q], p2[q], l2[q]);

            u64 dd[8] = { da.x, da.y, db.x, db.y, dc.x, dc.y, dd4.x, dd4.y };
            u64 rr[8] = { ra.x, ra.y, rb.x, rb.y, rc.x, rc.y, rd4.x, rd4.y };

            #pragma unroll
            for (int c = 0; c < 8; c++) {
                #pragma unroll
                for (int q = 0; q < 4; q++) {
                    FMA2(acc[c][q], a2[q], dd[c]);
                    FMA2(acc[c][q], p2[q], rr[c]);
                }
            }
        }

        __syncwarp();
        #pragma unroll
        for (int c = 0; c < 8; c++) {
            int col = (c < 4) ? (4 * cg + c) : (28 + 4 * cg + c);
            u64* dst = reinterpret_cast<u64*>(Pw + col * PSTRIDE + 8 * pg);
            #pragma unroll
            for (int q = 0; q < 4; q++) dst[q] = acc[c][q];
        }
        __syncwarp();
    }

    // ------- folded final step: 16 classes, lane tile 8 pts x 2 classes -------
    {
        u64 fac[2][4];
        #pragma unroll
        for (int ci = 0; ci < 2; ci++)
            #pragma unroll
            for (int q = 0; q < 4; q++) fac[ci][q] = 0ull;

        #pragma unroll 2
        for (int n = 0; n < N_NODES; ++n) {
            u64 dpair = *reinterpret_cast<const u64*>(DCs + n * N_CLASSES + 2 * cg);
            u64 rpair = *reinterpret_cast<const u64*>(RCs + n * N_CLASSES + 2 * cg);
            float dc0, dc1, rc0, rc1;
            UNPACK2(dc0, dc1, dpair);
            UNPACK2(rc0, rc1, rpair);

            const float* prow = Pw  + n * PSTRIDE + 8 * pg;
            const float* lrow = Lfw + n * PSTRIDE + 8 * pg;
            ulonglong2 pA = *reinterpret_cast<const ulonglong2*>(prow);
            ulonglong2 pB = *reinterpret_cast<const ulonglong2*>(prow + 4);
            ulonglong2 lA = *reinterpret_cast<const ulonglong2*>(lrow);
            ulonglong2 lB = *reinterpret_cast<const ulonglong2*>(lrow + 4);

            u64 p2[4] = { pA.x, pA.y, pB.x, pB.y };
            u64 l2[4] = { lA.x, lA.y, lB.x, lB.y };
            u64 a2[4];
            #pragma unroll
            for (int q = 0; q < 4; q++) MUL2(a2[q], p2[q], l2[q]);

            u64 dd0, dd1, rr0, rr1;
            PACK_DUP(dd0, dc0); PACK_DUP(dd1, dc1);
            PACK_DUP(rr0, rc0); PACK_DUP(rr1, rc1);
            #pragma unroll
            for (int q = 0; q < 4; q++) {
                FMA2(fac[0][q], a2[q], dd0);
                FMA2(fac[0][q], p2[q], rr0);
                FMA2(fac[1][q], a2[q], dd1);
                FMA2(fac[1][q], p2[q], rr1);
            }
        }

        __syncwarp();
        #pragma unroll
        for (int ci = 0; ci < 2; ci++) {
            int cls = 2 * cg + ci;
            u64* dst = reinterpret_cast<u64*>(Pw + cls * PSTRIDE + 8 * pg);
            #pragma unroll
            for (int q = 0; q < 4; q++) dst[q] = fac[ci][q];
        }
        __syncwarp();
    }

    // ------- gather own point, normalize, store -------
    if (inr) {
        float o[16], s = 0.0f;
        #pragma unroll
        for (int c = 0; c < 16; c++) { o[c] = Pw[c * PSTRIDE + lane]; s += o[c]; }
        float inv = 1.0f / fmaxf(s, 1e-10f);
        float4* o4 = reinterpret_cast<float4*>(out + my_pt * N_CLASSES);
        #pragma unroll
        for (int k = 0; k < 4; k++) {
            float4 v;
            v.x = o[4 * k] * inv;     v.y = o[4 * k + 1] * inv;
            v.z = o[4 * k + 2] * inv; v.w = o[4 * k + 3] * inv;
            o4[k] = v;
        }
    }
}

// ---------------------------------------------------------------------------
extern "C" void kernel_launch(void* const* d_in, const int* in_sizes, int n_in,
                              void* d_out, int out_size) {
    const float* x_pos = (const float*)d_in[0];
    const float* y_pos = (const float*)d_in[1];
    const float* sp    = (const float*)d_in[2];
    const float* dirl  = (const float*)d_in[3];
    const float* cls   = (const float*)d_in[4];
    const float* child = (const float*)d_in[5];
    const void*  mdp   = d_in[6];
    float* out = (float*)d_out;

    int B = in_sizes[0];

    cudaFuncSetAttribute(fractal_main_kernel,
                         cudaFuncAttributeMaxDynamicSharedMemorySize, SMEM_BYTES);

    fractal_setup_kernel<<<1, 64>>>(sp, dirl, cls, child);

    int grid = (B + TPB - 1) / TPB;
    fractal_main_kernel<<<grid, TPB, SMEM_BYTES>>>(x_pos, y_pos, mdp, out, B);
}

// round 10
// speedup vs baseline: 1.3601x; 1.3601x over previous
#include <cuda_runtime.h>
#include <cuda_bf16.h>

// Fractal2DDiff — SIMT f32x2 v5: R7 memory pattern (wf-minimal) + unroll-4
// latency hiding + STS.128 writeback.
//  * rank-1 analytic first step, folded final step (D@CP, R@CP),
//    single end normalization (L,R row-stochastic).
//  * 10 warps / 320 threads, ~226KB smem, one CTA per SM.

#define N_NODES   64
#define N_CLASSES 16
#define WARPS     10
#define TPB       (WARPS * 32)
#define PSTRIDE   36   // floats per p/left row (32 + pad)

typedef unsigned long long u64;

__device__ float g_D[N_NODES * N_NODES];      // L - R
__device__ float g_R[N_NODES * N_NODES];      // R
__device__ float g_DC[N_NODES * N_CLASSES];   // D @ CP
__device__ float g_RC[N_NODES * N_CLASSES];   // R @ CP
__device__ float g_par[256];                  // exp(-sp) | dirs | D row0 | R row0

// ---------------------------------------------------------------------------
__global__ void fractal_setup_kernel(const float* __restrict__ sp,
                                     const float* __restrict__ dir_logits,
                                     const float* __restrict__ class_logits,
                                     const float* __restrict__ child_logits) {
    __shared__ float sCP[N_NODES * N_CLASSES];
    int t = threadIdx.x;   // 64 threads, t = node

    {   // CP row t
        const float* cr = class_logits + t * N_CLASSES;
        float m = -1e30f;
        for (int i = 0; i < N_CLASSES; i++) m = fmaxf(m, cr[i]);
        float s = 0.0f;
        for (int i = 0; i < N_CLASSES; i++) s += expf(cr[i] - m);
        float inv = 1.0f / s;
        for (int i = 0; i < N_CLASSES; i++) sCP[t * N_CLASSES + i] = expf(cr[i] - m) * inv;
    }
    __syncthreads();

    const float* lr = child_logits + (size_t)t * 2 * N_NODES;
    const float* rr = lr + N_NODES;
    float Lv[64], Rv[64], Dv[64];
    {
        float m = -1e30f;
        for (int i = 0; i < 64; i++) m = fmaxf(m, lr[i]);
        float s = 0.0f;
        for (int i = 0; i < 64; i++) s += expf(lr[i] - m);
        float inv = 1.0f / s;
        for (int i = 0; i < 64; i++) Lv[i] = expf(lr[i] - m) * inv;
    }
    {
        float m = -1e30f;
        for (int i = 0; i < 64; i++) m = fmaxf(m, rr[i]);
        float s = 0.0f;
        for (int i = 0; i < 64; i++) s += expf(rr[i] - m);
        float inv = 1.0f / s;
        for (int i = 0; i < 64; i++) Rv[i] = expf(rr[i] - m) * inv;
    }
    for (int i = 0; i < 64; i++) {
        Dv[i] = Lv[i] - Rv[i];
        g_D[t * 64 + i] = Dv[i];
        g_R[t * 64 + i] = Rv[i];
    }
    for (int jc = 0; jc < N_CLASSES; jc++) {
        float ds = 0.0f, rs = 0.0f;
        for (int j = 0; j < 64; j++) {
            ds += Dv[j] * sCP[j * N_CLASSES + jc];
            rs += Rv[j] * sCP[j * N_CLASSES + jc];
        }
        g_DC[t * N_CLASSES + jc] = ds;
        g_RC[t * N_CLASSES + jc] = rs;
    }
    g_par[t]      = expf(-sp[t]);
    g_par[64 + t] = 1.0f / (1.0f + expf(-dir_logits[t]));
    if (t == 0)
        for (int j = 0; j < 64; j++) { g_par[128 + j] = Dv[j]; g_par[192 + j] = Rv[j]; }
}

// Packed f32x2 helpers (sm_103a)
#define FMA2(acc, a, b) \
    asm("fma.rn.f32x2 %0, %1, %2, %0;" : "+l"(acc) : "l"(a), "l"(b))
#define MUL2(d, a, b) \
    asm("mul.rn.f32x2 %0, %1, %2;" : "=l"(d) : "l"(a), "l"(b))
#define PACK_DUP(d, s) \
    asm("mov.b64 %0, {%1, %1};" : "=l"(d) : "f"(s))
#define UNPACK2(lo, hi, v) \
    asm("mov.b64 {%0, %1}, %2;" : "=f"(lo), "=f"(hi) : "l"(v))

__device__ __forceinline__ int decode_depth(const void* mdp) {
    int v = *reinterpret_cast<const int*>(mdp);
    if (v >= 1 && v <= 1000) return v;
    float f = __int_as_float(v);
    if (f >= 1.0f && f <= 1000.0f) return (int)f;
    return 10;
}

// smem floats: Ds 4096 | Rs 4096 | DCs 1024 | RCs 1024 | PAR 256 |
//              state WARPS * 2 * 64 * PSTRIDE
#define SMEM_FLOATS (4096 + 4096 + 1024 + 1024 + 256 + WARPS * 2 * 64 * PSTRIDE)
#define SMEM_BYTES  (SMEM_FLOATS * 4)

__global__ __launch_bounds__(TPB, 1)
void fractal_main_kernel(const float* __restrict__ x_pos,
                         const float* __restrict__ y_pos,
                         const void*  __restrict__ max_depth_ptr,
                         float* __restrict__ out,
                         int B) {
    extern __shared__ float sm[];
    float* Ds  = sm;
    float* Rs  = Ds + 4096;
    float* DCs = Rs + 4096;
    float* RCs = DCs + 1024;
    float* PAR = RCs + 1024;
    float* ST  = PAR + 256;

    const int tid  = threadIdx.x;
    const int wid  = tid >> 5;
    const int lane = tid & 31;
    const int cg   = lane & 7;    // col group
    const int pg   = lane >> 3;   // point group (4 groups x 8 pts)

    for (int i = tid; i < 4096; i += TPB) { Ds[i] = g_D[i]; Rs[i] = g_R[i]; }
    for (int i = tid; i < 1024; i += TPB) { DCs[i] = g_DC[i]; RCs[i] = g_RC[i]; }
    if (tid < 256) PAR[tid] = g_par[tid];
    __syncthreads();

    float* Pw  = ST + wid * (2 * 64 * PSTRIDE);
    float* Lfw = Pw + 64 * PSTRIDE;

    const long long my_pt = (long long)blockIdx.x * TPB + wid * 32 + lane;
    const bool inr = (my_pt < B);

    int md = decode_depth(max_depth_ptr);
    if (md < 2) md = 2;
    const int full_iters = md - 2;

    const float x = inr ? x_pos[my_pt] : 0.5f;
    const float y = inr ? y_pos[my_pt] : 0.5f;
    const float ex = __expf(x), ey = __expf(y);

    // left[n] for own point (own smem column, no cross-thread hazard)
    #pragma unroll 8
    for (int n = 0; n < N_NODES; ++n) {
        float tn = PAR[n], d = PAR[64 + n];
        float hl = __fdividef(1.0f, 1.0f + ex * tn);   // sigmoid(sp-x)
        float vl = __fdividef(1.0f, 1.0f + ey * tn);   // sigmoid(sp-y)
        Lfw[n * PSTRIDE + lane] = hl + d * (vl - hl);
    }
    // rank-1 first step: p1 = R[0,:] + left0 * D[0,:]
    float l0;
    {
        float t0 = PAR[0], d0 = PAR[64];
        float hl = __fdividef(1.0f, 1.0f + ex * t0);
        float vl = __fdividef(1.0f, 1.0f + ey * t0);
        l0 = hl + d0 * (vl - hl);
    }
    #pragma unroll 8
    for (int n = 0; n < N_NODES; ++n)
        Pw[n * PSTRIDE + lane] = fmaf(l0, PAR[128 + n], PAR[192 + n]);
    __syncwarp();

    // ------- full iterations: acc[c][q], c=8 cols, q=4 point-pairs -------
    for (int it = 0; it < full_iters; ++it) {
        u64 acc[8][4];
        #pragma unroll
        for (int c = 0; c < 8; c++)
            #pragma unroll
            for (int q = 0; q < 4; q++) acc[c][q] = 0ull;

        #pragma unroll 4
        for (int n = 0; n < N_NODES; ++n) {
            const float* drow = Ds + n * 64;
            const float* rrow = Rs + n * 64;
            ulonglong2 dlo = *reinterpret_cast<const ulonglong2*>(drow + 4 * cg);
            ulonglong2 dhi = *reinterpret_cast<const ulonglong2*>(drow + 32 + 4 * cg);
            ulonglong2 rlo = *reinterpret_cast<const ulonglong2*>(rrow + 4 * cg);
            ulonglong2 rhi = *reinterpret_cast<const ulonglong2*>(rrow + 32 + 4 * cg);

            const float* prow = Pw  + n * PSTRIDE + 8 * pg;
            const float* lrow = Lfw + n * PSTRIDE + 8 * pg;
            ulonglong2 pA = *reinterpret_cast<const ulonglong2*>(prow);
            ulonglong2 pB = *reinterpret_cast<const ulonglong2*>(prow + 4);
            ulonglong2 lA = *reinterpret_cast<const ulonglong2*>(lrow);
            ulonglong2 lB = *reinterpret_cast<const ulonglong2*>(lrow + 4);

            u64 p2[4] = { pA.x, pA.y, pB.x, pB.y };
            u64 l2[4] = { lA.x, lA.y, lB.x, lB.y };
            u64 a2[4];
            #pragma unroll
            for (int q = 0; q < 4; q++) MUL2(a2[q], p2[q], l2[q]);

            float dsc[8], rsc[8];
            UNPACK2(dsc[0], dsc[1], dlo.x); UNPACK2(dsc[2], dsc[3], dlo.y);
            UNPACK2(dsc[4], dsc[5], dhi.x); UNPACK2(dsc[6], dsc[7], dhi.y);
            UNPACK2(rsc[0], rsc[1], rlo.x); UNPACK2(rsc[2], rsc[3], rlo.y);
            UNPACK2(rsc[4], rsc[5], rhi.x); UNPACK2(rsc[6], rsc[7], rhi.y);

            #pragma unroll
            for (int c = 0; c < 8; c++) {
                u64 dd, rr;
                PACK_DUP(dd, dsc[c]);
                PACK_DUP(rr, rsc[c]);
                #pragma unroll
                for (int q = 0; q < 4; q++) {
                    FMA2(acc[c][q], a2[q], dd);
                    FMA2(acc[c][q], p2[q], rr);
                }
            }
        }

        __syncwarp();
        #pragma unroll
        for (int c = 0; c < 8; c++) {
            int col = (c < 4) ? (4 * cg + c) : (28 + 4 * cg + c);
            ulonglong2* dst = reinterpret_cast<ulonglong2*>(Pw + col * PSTRIDE + 8 * pg);
            ulonglong2 v0; v0.x = acc[c][0]; v0.y = acc[c][1];
            ulonglong2 v1; v1.x = acc[c][2]; v1.y = acc[c][3];
            dst[0] = v0;
            dst[1] = v1;
        }
        __syncwarp();
    }

    // ------- folded final step: 16 classes, lane tile 8 pts x 2 classes -------
    {
        u64 fac[2][4];
        #pragma unroll
        for (int ci = 0; ci < 2; ci++)
            #pragma unroll
            for (int q = 0; q < 4; q++) fac[ci][q] = 0ull;

        #pragma unroll 4
        for (int n = 0; n < N_NODES; ++n) {
            u64 dpair = *reinterpret_cast<const u64*>(DCs + n * N_CLASSES + 2 * cg);
            u64 rpair = *reinterpret_cast<const u64*>(RCs + n * N_CLASSES + 2 * cg);
            float dc0, dc1, rc0, rc1;
            UNPACK2(dc0, dc1, dpair);
            UNPACK2(rc0, rc1, rpair);

            const float* prow = Pw  + n * PSTRIDE + 8 * pg;
            const float* lrow = Lfw + n * PSTRIDE + 8 * pg;
            ulonglong2 pA = *reinterpret_cast<const ulonglong2*>(prow);
            ulonglong2 pB = *reinterpret_cast<const ulonglong2*>(prow + 4);
            ulonglong2 lA = *reinterpret_cast<const ulonglong2*>(lrow);
            ulonglong2 lB = *reinterpret_cast<const ulonglong2*>(lrow + 4);

            u64 p2[4] = { pA.x, pA.y, pB.x, pB.y };
            u64 l2[4] = { lA.x, lA.y, lB.x, lB.y };
            u64 a2[4];
            #pragma unroll
            for (int q = 0; q < 4; q++) MUL2(a2[q], p2[q], l2[q]);

            u64 dd0, dd1, rr0, rr1;
            PACK_DUP(dd0, dc0); PACK_DUP(dd1, dc1);
            PACK_DUP(rr0, rc0); PACK_DUP(rr1, rc1);
            #pragma unroll
            for (int q = 0; q < 4; q++) {
                FMA2(fac[0][q], a2[q], dd0);
                FMA2(fac[0][q], p2[q], rr0);
                FMA2(fac[1][q], a2[q], dd1);
                FMA2(fac[1][q], p2[q], rr1);
            }
        }

        __syncwarp();
        #pragma unroll
        for (int ci = 0; ci < 2; ci++) {
            int cls = 2 * cg + ci;
            ulonglong2* dst = reinterpret_cast<ulonglong2*>(Pw + cls * PSTRIDE + 8 * pg);
            ulonglong2 v0; v0.x = fac[ci][0]; v0.y = fac[ci][1];
            ulonglong2 v1; v1.x = fac[ci][2]; v1.y = fac[ci][3];
            dst[0] = v0;
            dst[1] = v1;
        }
        __syncwarp();
    }

    // ------- gather own point, normalize, store -------
    if (inr) {
        float o[16], s = 0.0f;
        #pragma unroll
        for (int c = 0; c < 16; c++) { o[c] = Pw[c * PSTRIDE + lane]; s += o[c]; }
        float inv = 1.0f / fmaxf(s, 1e-10f);
        float4* o4 = reinterpret_cast<float4*>(out + my_pt * N_CLASSES);
        #pragma unroll
        for (int k = 0; k < 4; k++) {
            float4 v;
            v.x = o[4 * k] * inv;     v.y = o[4 * k + 1] * inv;
            v.z = o[4 * k + 2] * inv; v.w = o[4 * k + 3] * inv;
            o4[k] = v;
        }
    }
}

// ---------------------------------------------------------------------------
extern "C" void kernel_launch(void* const* d_in, const int* in_sizes, int n_in,
                              void* d_out, int out_size) {
    const float* x_pos = (const float*)d_in[0];
    const float* y_pos = (const float*)d_in[1];
    const float* sp    = (const float*)d_in[2];
    const float* dirl  = (const float*)d_in[3];
    const float* cls   = (const float*)d_in[4];
    const float* child = (const float*)d_in[5];
    const void*  mdp   = d_in[6];
    float* out = (float*)d_out;

    int B = in_sizes[0];

    cudaFuncSetAttribute(fractal_main_kernel,
                         cudaFuncAttributeMaxDynamicSharedMemorySize, SMEM_BYTES);

    fractal_setup_kernel<<<1, 64>>>(sp, dirl, cls, child);

    int grid = (B + TPB - 1) / TPB;
    fractal_main_kernel<<<grid, TPB, SMEM_BYTES>>>(x_pos, y_pos, mdp, out, B);
}

// round 11
// speedup vs baseline: 1.4100x; 1.0367x over previous
#include <cuda_runtime.h>
#include <cuda_bf16.h>

// Fractal2DDiff — SIMT f32x2 v6: persistent blocks + unroll-8 node loop.
//  * grid = 148 persistent CTAs (1/SM), each loops over 320-point batches:
//    tables loaded to smem once, no wave-quantization tail.
//  * rank-1 analytic first step, folded final step (D@CP, R@CP),
//    single end normalization (L,R row-stochastic).
//  * 10 warps / 320 threads, ~221KB smem.

#define N_NODES   64
#define N_CLASSES 16
#define WARPS     10
#define TPB       (WARPS * 32)
#define PSTRIDE   36   // floats per p/left row (32 + pad)

typedef unsigned long long u64;

__device__ float g_D[N_NODES * N_NODES];      // L - R
__device__ float g_R[N_NODES * N_NODES];      // R
__device__ float g_DC[N_NODES * N_CLASSES];   // D @ CP
__device__ float g_RC[N_NODES * N_CLASSES];   // R @ CP
__device__ float g_par[256];                  // exp(-sp) | dirs | D row0 | R row0

// ---------------------------------------------------------------------------
__global__ void fractal_setup_kernel(const float* __restrict__ sp,
                                     const float* __restrict__ dir_logits,
                                     const float* __restrict__ class_logits,
                                     const float* __restrict__ child_logits) {
    __shared__ float sCP[N_NODES * N_CLASSES];
    int t = threadIdx.x;   // 64 threads, t = node

    {   // CP row t
        const float* cr = class_logits + t * N_CLASSES;
        float m = -1e30f;
        for (int i = 0; i < N_CLASSES; i++) m = fmaxf(m, cr[i]);
        float s = 0.0f;
        for (int i = 0; i < N_CLASSES; i++) s += expf(cr[i] - m);
        float inv = 1.0f / s;
        for (int i = 0; i < N_CLASSES; i++) sCP[t * N_CLASSES + i] = expf(cr[i] - m) * inv;
    }
    __syncthreads();

    const float* lr = child_logits + (size_t)t * 2 * N_NODES;
    const float* rr = lr + N_NODES;
    float Lv[64], Rv[64], Dv[64];
    {
        float m = -1e30f;
        for (int i = 0; i < 64; i++) m = fmaxf(m, lr[i]);
        float s = 0.0f;
        for (int i = 0; i < 64; i++) s += expf(lr[i] - m);
        float inv = 1.0f / s;
        for (int i = 0; i < 64; i++) Lv[i] = expf(lr[i] - m) * inv;
    }
    {
        float m = -1e30f;
        for (int i = 0; i < 64; i++) m = fmaxf(m, rr[i]);
        float s = 0.0f;
        for (int i = 0; i < 64; i++) s += expf(rr[i] - m);
        float inv = 1.0f / s;
        for (int i = 0; i < 64; i++) Rv[i] = expf(rr[i] - m) * inv;
    }
    for (int i = 0; i < 64; i++) {
        Dv[i] = Lv[i] - Rv[i];
        g_D[t * 64 + i] = Dv[i];
        g_R[t * 64 + i] = Rv[i];
    }
    for (int jc = 0; jc < N_CLASSES; jc++) {
        float ds = 0.0f, rs = 0.0f;
        for (int j = 0; j < 64; j++) {
            ds += Dv[j] * sCP[j * N_CLASSES + jc];
            rs += Rv[j] * sCP[j * N_CLASSES + jc];
        }
        g_DC[t * N_CLASSES + jc] = ds;
        g_RC[t * N_CLASSES + jc] = rs;
    }
    g_par[t]      = expf(-sp[t]);
    g_par[64 + t] = 1.0f / (1.0f + expf(-dir_logits[t]));
    if (t == 0)
        for (int j = 0; j < 64; j++) { g_par[128 + j] = Dv[j]; g_par[192 + j] = Rv[j]; }
}

// Packed f32x2 helpers (sm_103a)
#define FMA2(acc, a, b) \
    asm("fma.rn.f32x2 %0, %1, %2, %0;" : "+l"(acc) : "l"(a), "l"(b))
#define MUL2(d, a, b) \
    asm("mul.rn.f32x2 %0, %1, %2;" : "=l"(d) : "l"(a), "l"(b))
#define PACK_DUP(d, s) \
    asm("mov.b64 %0, {%1, %1};" : "=l"(d) : "f"(s))
#define UNPACK2(lo, hi, v) \
    asm("mov.b64 {%0, %1}, %2;" : "=f"(lo), "=f"(hi) : "l"(v))

__device__ __forceinline__ int decode_depth(const void* mdp) {
    int v = *reinterpret_cast<const int*>(mdp);
    if (v >= 1 && v <= 1000) return v;
    float f = __int_as_float(v);
    if (f >= 1.0f && f <= 1000.0f) return (int)f;
    return 10;
}

// smem floats: Ds 4096 | Rs 4096 | DCs 1024 | RCs 1024 | PAR 256 |
//              state WARPS * 2 * 64 * PSTRIDE
#define SMEM_FLOATS (4096 + 4096 + 1024 + 1024 + 256 + WARPS * 2 * 64 * PSTRIDE)
#define SMEM_BYTES  (SMEM_FLOATS * 4)

__global__ __launch_bounds__(TPB, 1)
void fractal_main_kernel(const float* __restrict__ x_pos,
                         const float* __restrict__ y_pos,
                         const void*  __restrict__ max_depth_ptr,
                         float* __restrict__ out,
                         int B, int nbatch) {
    extern __shared__ float sm[];
    float* Ds  = sm;
    float* Rs  = Ds + 4096;
    float* DCs = Rs + 4096;
    float* RCs = DCs + 1024;
    float* PAR = RCs + 1024;
    float* ST  = PAR + 256;

    const int tid  = threadIdx.x;
    const int wid  = tid >> 5;
    const int lane = tid & 31;
    const int cg   = lane & 7;    // col group
    const int pg   = lane >> 3;   // point group (4 groups x 8 pts)

    for (int i = tid; i < 4096; i += TPB) { Ds[i] = g_D[i]; Rs[i] = g_R[i]; }
    for (int i = tid; i < 1024; i += TPB) { DCs[i] = g_DC[i]; RCs[i] = g_RC[i]; }
    if (tid < 256) PAR[tid] = g_par[tid];
    __syncthreads();

    float* Pw  = ST + wid * (2 * 64 * PSTRIDE);
    float* Lfw = Pw + 64 * PSTRIDE;

    int md = decode_depth(max_depth_ptr);
    if (md < 2) md = 2;
    const int full_iters = md - 2;

    // Persistent batch loop: batch bi covers points [bi*TPB, bi*TPB+TPB).
    for (int bi = blockIdx.x; bi < nbatch; bi += gridDim.x) {
        __syncwarp();   // prior batch's cross-lane state reads complete

        const long long my_pt = (long long)bi * TPB + wid * 32 + lane;
        const bool inr = (my_pt < B);

        const float x = inr ? x_pos[my_pt] : 0.5f;
        const float y = inr ? y_pos[my_pt] : 0.5f;
        const float ex = __expf(x), ey = __expf(y);

        // left[n] for own point (own smem column, no cross-thread hazard)
        #pragma unroll 8
        for (int n = 0; n < N_NODES; ++n) {
            float tn = PAR[n], d = PAR[64 + n];
            float hl = __fdividef(1.0f, 1.0f + ex * tn);   // sigmoid(sp-x)
            float vl = __fdividef(1.0f, 1.0f + ey * tn);   // sigmoid(sp-y)
            Lfw[n * PSTRIDE + lane] = hl + d * (vl - hl);
        }
        // rank-1 first step: p1 = R[0,:] + left0 * D[0,:]
        float l0;
        {
            float t0 = PAR[0], d0 = PAR[64];
            float hl = __fdividef(1.0f, 1.0f + ex * t0);
            float vl = __fdividef(1.0f, 1.0f + ey * t0);
            l0 = hl + d0 * (vl - hl);
        }
        #pragma unroll 8
        for (int n = 0; n < N_NODES; ++n)
            Pw[n * PSTRIDE + lane] = fmaf(l0, PAR[128 + n], PAR[192 + n]);
        __syncwarp();

        // ------- full iterations: acc[c][q], c=8 cols, q=4 point-pairs -------
        for (int it = 0; it < full_iters; ++it) {
            u64 acc[8][4];
            #pragma unroll
            for (int c = 0; c < 8; c++)
                #pragma unroll
                for (int q = 0; q < 4; q++) acc[c][q] = 0ull;

            #pragma unroll 8
            for (int n = 0; n < N_NODES; ++n) {
                const float* drow = Ds + n * 64;
                const float* rrow = Rs + n * 64;
                ulonglong2 dlo = *reinterpret_cast<const ulonglong2*>(drow + 4 * cg);
                ulonglong2 dhi = *reinterpret_cast<const ulonglong2*>(drow + 32 + 4 * cg);
                ulonglong2 rlo = *reinterpret_cast<const ulonglong2*>(rrow + 4 * cg);
                ulonglong2 rhi = *reinterpret_cast<const ulonglong2*>(rrow + 32 + 4 * cg);

                const float* prow = Pw  + n * PSTRIDE + 8 * pg;
                const float* lrow = Lfw + n * PSTRIDE + 8 * pg;
                ulonglong2 pA = *reinterpret_cast<const ulonglong2*>(prow);
                ulonglong2 pB = *reinterpret_cast<const ulonglong2*>(prow + 4);
                ulonglong2 lA = *reinterpret_cast<const ulonglong2*>(lrow);
                ulonglong2 lB = *reinterpret_cast<const ulonglong2*>(lrow + 4);

                u64 p2[4] = { pA.x, pA.y, pB.x, pB.y };
                u64 l2[4] = { lA.x, lA.y, lB.x, lB.y };
                u64 a2[4];
                #pragma unroll
                for (int q = 0; q < 4; q++) MUL2(a2[q], p2[q], l2[q]);

                float dsc[8], rsc[8];
                UNPACK2(dsc[0], dsc[1], dlo.x); UNPACK2(dsc[2], dsc[3], dlo.y);
                UNPACK2(dsc[4], dsc[5], dhi.x); UNPACK2(dsc[6], dsc[7], dhi.y);
                UNPACK2(rsc[0], rsc[1], rlo.x); UNPACK2(rsc[2], rsc[3], rlo.y);
                UNPACK2(rsc[4], rsc[5], rhi.x); UNPACK2(rsc[6], rsc[7], rhi.y);

                #pragma unroll
                for (int c = 0; c < 8; c++) {
                    u64 dd, rr;
                    PACK_DUP(dd, dsc[c]);
                    PACK_DUP(rr, rsc[c]);
                    #pragma unroll
                    for (int q = 0; q < 4; q++) {
                        FMA2(acc[c][q], a2[q], dd);
                        FMA2(acc[c][q], p2[q], rr);
                    }
                }
            }

            __syncwarp();
            #pragma unroll
            for (int c = 0; c < 8; c++) {
                int col = (c < 4) ? (4 * cg + c) : (28 + 4 * cg + c);
                ulonglong2* dst = reinterpret_cast<ulonglong2*>(Pw + col * PSTRIDE + 8 * pg);
                ulonglong2 v0; v0.x = acc[c][0]; v0.y = acc[c][1];
                ulonglong2 v1; v1.x = acc[c][2]; v1.y = acc[c][3];
                dst[0] = v0;
                dst[1] = v1;
            }
            __syncwarp();
        }

        // ------- folded final step: 16 classes, lane tile 8 pts x 2 classes -------
        {
            u64 fac[2][4];
            #pragma unroll
            for (int ci = 0; ci < 2; ci++)
                #pragma unroll
                for (int q = 0; q < 4; q++) fac[ci][q] = 0ull;

            #pragma unroll 4
            for (int n = 0; n < N_NODES; ++n) {
                u64 dpair = *reinterpret_cast<const u64*>(DCs + n * N_CLASSES + 2 * cg);
                u64 rpair = *reinterpret_cast<const u64*>(RCs + n * N_CLASSES + 2 * cg);
                float dc0, dc1, rc0, rc1;
                UNPACK2(dc0, dc1, dpair);
                UNPACK2(rc0, rc1, rpair);

                const float* prow = Pw  + n * PSTRIDE + 8 * pg;
                const float* lrow = Lfw + n * PSTRIDE + 8 * pg;
                ulonglong2 pA = *reinterpret_cast<const ulonglong2*>(prow);
                ulonglong2 pB = *reinterpret_cast<const ulonglong2*>(prow + 4);
                ulonglong2 lA = *reinterpret_cast<const ulonglong2*>(lrow);
                ulonglong2 lB = *reinterpret_cast<const ulonglong2*>(lrow + 4);

                u64 p2[4] = { pA.x, pA.y, pB.x, pB.y };
                u64 l2[4] = { lA.x, lA.y, lB.x, lB.y };
                u64 a2[4];
                #pragma unroll
                for (int q = 0; q < 4; q++) MUL2(a2[q], p2[q], l2[q]);

                u64 dd0, dd1, rr0, rr1;
                PACK_DUP(dd0, dc0); PACK_DUP(dd1, dc1);
                PACK_DUP(rr0, rc0); PACK_DUP(rr1, rc1);
                #pragma unroll
                for (int q = 0; q < 4; q++) {
                    FMA2(fac[0][q], a2[q], dd0);
                    FMA2(fac[0][q], p2[q], rr0);
                    FMA2(fac[1][q], a2[q], dd1);
                    FMA2(fac[1][q], p2[q], rr1);
                }
            }

            __syncwarp();
            #pragma unroll
            for (int ci = 0; ci < 2; ci++) {
                int cls = 2 * cg + ci;
                ulonglong2* dst = reinterpret_cast<ulonglong2*>(Pw + cls * PSTRIDE + 8 * pg);
                ulonglong2 v0; v0.x = fac[ci][0]; v0.y = fac[ci][1];
                ulonglong2 v1; v1.x = fac[ci][2]; v1.y = fac[ci][3];
                dst[0] = v0;
                dst[1] = v1;
            }
            __syncwarp();
        }

        // ------- gather own point, normalize, store -------
        if (inr) {
            float o[16], s = 0.0f;
            #pragma unroll
            for (int c = 0; c < 16; c++) { o[c] = Pw[c * PSTRIDE + lane]; s += o[c]; }
            float inv = 1.0f / fmaxf(s, 1e-10f);
            float4* o4 = reinterpret_cast<float4*>(out + my_pt * N_CLASSES);
            #pragma unroll
            for (int k = 0; k < 4; k++) {
                float4 v;
                v.x = o[4 * k] * inv;     v.y = o[4 * k + 1] * inv;
                v.z = o[4 * k + 2] * inv; v.w = o[4 * k + 3] * inv;
                o4[k] = v;
            }
        }
    }
}

// ---------------------------------------------------------------------------
extern "C" void kernel_launch(void* const* d_in, const int* in_sizes, int n_in,
                              void* d_out, int out_size) {
    const float* x_pos = (const float*)d_in[0];
    const float* y_pos = (const float*)d_in[1];
    const float* sp    = (const float*)d_in[2];
    const float* dirl  = (const float*)d_in[3];
    const float* cls   = (const float*)d_in[4];
    const float* child = (const float*)d_in[5];
    const void*  mdp   = d_in[6];
    float* out = (float*)d_out;

    int B = in_sizes[0];
    int nbatch = (B + TPB - 1) / TPB;
    int grid = nbatch < 148 ? nbatch : 148;

    cudaFuncSetAttribute(fractal_main_kernel,
                         cudaFuncAttributeMaxDynamicSharedMemorySize, SMEM_BYTES);

    fractal_setup_kernel<<<1, 64>>>(sp, dirl, cls, child);

    fractal_main_kernel<<<grid, TPB, SMEM_BYTES>>>(x_pos, y_pos, mdp, out, B, nbatch);
}